// round 9
// baseline (speedup 1.0000x reference)
#include <cuda_runtime.h>
#include <cuda_bf16.h>
#include <cstdint>

#define NPTS   8192
#define CH     32
#define TILE   256
#define MT     32                      // NPTS / TILE
#define NTILES 528                     // MT*(MT+1)/2 upper-triangle tile pairs
#define NPREP  128                     // prep blocks (8192 / 64)
#define PQ     12                      // padded row stride in b32 words (48B; 32B used)

// ---------------- device scratch (no allocations allowed) -------------------
__device__ float    g_sq[NPTS];           // full 32-ch tree norms (exact path)
__device__ float    g_sq16[NPTS];         // first-16-ch norms (screen only)
__device__ uint32_t g_xbf[NPTS * 8];      // [n][8] bf16x2 words: channels 0..15
__device__ float    g_partial[NTILES];
__device__ float    g_diagpart[NPREP];
__device__ int      g_counter;            // zero-init; reset by last CTA

// ---------------------------------------------------------------------------
// Kernel A (prep): per-point full tree-sq + sequential-FMA self-dot -> exact
// diagonal loss (bit-identical arithmetic to the passing R2..R8 pipeline),
// 16-ch screen norm, and bf16 pack of channels 0..15 (staged via smem).
// ---------------------------------------------------------------------------
__global__ __launch_bounds__(64) void prep_kernel(const float* __restrict__ x) {
    __shared__ uint32_t s8[64 * 8];
    __shared__ float    red[64];

    int tid = threadIdx.x;
    int n = blockIdx.x * 64 + tid;

    float v[CH];
#pragma unroll
    for (int c = 0; c < CH; ++c) v[c] = x[c * NPTS + n];

    // full sq: non-FMA products, 4-accumulator tree (XLA-reduce flavor)
    float a0 = 0.f, a1 = 0.f, a2 = 0.f, a3 = 0.f;
#pragma unroll
    for (int c = 0; c < CH; c += 4) {
        a0 = __fadd_rn(a0, __fmul_rn(v[c + 0], v[c + 0]));
        a1 = __fadd_rn(a1, __fmul_rn(v[c + 1], v[c + 1]));
        a2 = __fadd_rn(a2, __fmul_rn(v[c + 2], v[c + 2]));
        a3 = __fadd_rn(a3, __fmul_rn(v[c + 3], v[c + 3]));
    }
    float sq = __fadd_rn(__fadd_rn(a0, a1), __fadd_rn(a2, a3));
    g_sq[n] = sq;

    // self-dot: sequential FMA chain (GEMM flavor) -> diagonal noise d2 ~ +-eps
    float dot = 0.f;
#pragma unroll
    for (int c = 0; c < CH; ++c) dot = fmaf(v[c], v[c], dot);

    float d2 = fmaf(-2.f, dot, __fadd_rn(sq, sq));
    float f = 0.f;
    if (d2 < 4.f) {
        d2 = fmaxf(d2, 0.f);
        float d = sqrtf(d2);
        f = fmaf(1.5f, d, fmaf(-0.5f, d2, -1.f));
    }

    // 16-ch screen norm
    float s16 = 0.f;
#pragma unroll
    for (int c = 0; c < 16; ++c) s16 = fmaf(v[c], v[c], s16);
    g_sq16[n] = s16;

    // bf16 pack of channels 0..15 -> 8 words, staged for coalesced store
#pragma unroll
    for (int w = 0; w < 8; ++w) {
        __nv_bfloat162 pk = __floats2bfloat162_rn(v[2 * w], v[2 * w + 1]);
        s8[tid * 8 + w] = *reinterpret_cast<uint32_t*>(&pk);
    }
    __syncthreads();
    uint32_t* dst = &g_xbf[blockIdx.x * 64 * 8];
#pragma unroll
    for (int i = tid; i < 512; i += 64) dst[i] = s8[i];

    // deterministic block reduction of diagonal contributions
    red[tid] = f;
    __syncthreads();
#pragma unroll
    for (int s = 32; s > 0; s >>= 1) {
        if (tid < s) red[tid] += red[tid + s];
        __syncthreads();
    }
    if (tid == 0) g_diagpart[blockIdx.x] = red[0];
}

// ---------------------------------------------------------------------------
// mma.sync m16n8k16 bf16 (sm_80+ baseline PTX; portable to plain sm_103).
// ---------------------------------------------------------------------------
__device__ __forceinline__ void hmma16816(float* c, const uint32_t* a, const uint32_t* b) {
    asm volatile(
        "mma.sync.aligned.m16n8k16.row.col.f32.bf16.bf16.f32 "
        "{%0,%1,%2,%3}, {%4,%5,%6,%7}, {%8,%9}, {%0,%1,%2,%3};"
        : "+f"(c[0]), "+f"(c[1]), "+f"(c[2]), "+f"(c[3])
        : "r"(a[0]), "r"(a[1]), "r"(a[2]), "r"(a[3]), "r"(b[0]), "r"(b[1]));
}

// ---------------------------------------------------------------------------
// Exact fp32 recompute of one pair (full 32 channels). Used on screen flags.
// ---------------------------------------------------------------------------
__device__ __forceinline__ float exact_pair(const float* __restrict__ x,
                                            int gi, int gj) {
    float dt = 0.f;
#pragma unroll
    for (int c = 0; c < CH; ++c)
        dt = fmaf(x[c * NPTS + gi], x[c * NPTS + gj], dt);
    float e2 = fmaf(-2.f, dt, g_sq[gi] + g_sq[gj]);
    if (e2 < 4.f) {
        e2 = fmaxf(e2, 0.f);
        float d = sqrtf(e2);
        return fmaf(1.5f, d, fmaf(-0.5f, e2, -1.f));
    }
    return 0.f;
}

// ---------------------------------------------------------------------------
// Kernel B (tile): one CTA per (I,J) 256x256 tile pair, J >= I, 8 warps.
// K=16 bf16 HMMA screen with BURST structure: per nj, 4 INDEPENDENT MMAs
// (mi=0..3) back-to-back to hide legacy-mma latency, then one screen pass
// over all 16 accumulator elements with a single rarity branch.
// Screen soundness: d2_full >= d2_16; flag at d2_16_bf16 < 6 (err <= 0.6,
// margin 2). Flagged pairs recomputed exactly in fp32; gi==gj skipped
// (diagonal handled in prep). Last CTA does deterministic final reduction.
// ---------------------------------------------------------------------------
__global__ __launch_bounds__(256, 4) void tile_kernel(const float* __restrict__ x,
                                                      float* __restrict__ out) {
    __shared__ __align__(16) uint32_t As[TILE * PQ];   // 12 KB
    __shared__ __align__(16) uint32_t Bs[TILE * PQ];   // 12 KB
    __shared__ float s16A[TILE];
    __shared__ float s16B[TILE];
    __shared__ float red[256];
    __shared__ bool  amlast;

    int tid = threadIdx.x;
    int wid = tid >> 5;
    int lane = tid & 31;

    // decode blockIdx -> (I, J) over upper triangle
    int bid = blockIdx.x;
    int I = 0, rem = bid;
    while (rem >= MT - I) { rem -= MT - I; ++I; }
    int J = I + rem;
    bool diag = (I == J);

    // fill tiles: thread t owns row t of A (and of B when off-diagonal)
    {
        int gA = I * TILE + tid;
        const uint4* srcA = reinterpret_cast<const uint4*>(&g_xbf[gA * 8]);
        uint4* dA = reinterpret_cast<uint4*>(As + tid * PQ);
        dA[0] = srcA[0];
        dA[1] = srcA[1];
        s16A[tid] = g_sq16[gA];
        if (!diag) {
            int gB = J * TILE + tid;
            const uint4* srcB = reinterpret_cast<const uint4*>(&g_xbf[gB * 8]);
            uint4* dB = reinterpret_cast<uint4*>(Bs + tid * PQ);
            dB[0] = srcB[0];
            dB[1] = srcB[1];
            s16B[tid] = g_sq16[gB];
        }
    }
    __syncthreads();

    const uint32_t* Bsrc = diag ? As : Bs;
    const float*    sjv  = diag ? s16A : s16B;

    int m0 = (wid & 3) * 64;     // row block of this warp (64 rows)
    int n0 = (wid >> 2) * 128;   // col block of this warp (128 cols)
    int qr = lane >> 2;          // 0..7
    int qc = lane & 3;           // 0..3

    // A fragments (K=16: one fragment per 16-row slab) + lane row norms
    uint32_t afr[4][4];
    float siv[4][2];
#pragma unroll
    for (int mi = 0; mi < 4; ++mi) {
        int r0 = m0 + mi * 16 + qr;
        int r1 = r0 + 8;
        afr[mi][0] = As[r0 * PQ + qc];
        afr[mi][1] = As[r1 * PQ + qc];
        afr[mi][2] = As[r0 * PQ + qc + 4];
        afr[mi][3] = As[r1 * PQ + qc + 4];
        siv[mi][0] = s16A[r0];
        siv[mi][1] = s16A[r1];
    }

    float local = 0.f;

#pragma unroll
    for (int nj = 0; nj < 16; ++nj) {
        int jrow = n0 + nj * 8 + qr;
        uint32_t b[2];
        b[0] = Bsrc[jrow * PQ + qc];
        b[1] = Bsrc[jrow * PQ + qc + 4];

        // burst: 4 independent MMAs, accumulators disjoint
        float acc[4][4];
#pragma unroll
        for (int mi = 0; mi < 4; ++mi) {
            acc[mi][0] = acc[mi][1] = acc[mi][2] = acc[mi][3] = 0.f;
            hmma16816(acc[mi], afr[mi], b);
        }

        int colb = n0 + nj * 8 + 2 * qc;
        float sj0 = sjv[colb];
        float sj1 = sjv[colb + 1];

        // screen all 16 elements; single rarity branch per nj
        float mn = 1e30f;
#pragma unroll
        for (int mi = 0; mi < 4; ++mi) {
            acc[mi][0] = fmaf(-2.f, acc[mi][0], siv[mi][0] + sj0);
            acc[mi][1] = fmaf(-2.f, acc[mi][1], siv[mi][0] + sj1);
            acc[mi][2] = fmaf(-2.f, acc[mi][2], siv[mi][1] + sj0);
            acc[mi][3] = fmaf(-2.f, acc[mi][3], siv[mi][1] + sj1);
            mn = fminf(mn, fminf(fminf(acc[mi][0], acc[mi][1]),
                                 fminf(acc[mi][2], acc[mi][3])));
        }

        if (mn < 6.f) {   // rare off-diagonal (~10% of warp-iterations diverge)
            int gj0 = J * TILE + colb;
#pragma unroll
            for (int mi = 0; mi < 4; ++mi) {
                int gi0 = I * TILE + m0 + mi * 16 + qr;
                int gi1 = gi0 + 8;
                if (acc[mi][0] < 6.f && gi0 != gj0)     local += exact_pair(x, gi0, gj0);
                if (acc[mi][1] < 6.f && gi0 != gj0 + 1) local += exact_pair(x, gi0, gj0 + 1);
                if (acc[mi][2] < 6.f && gi1 != gj0)     local += exact_pair(x, gi1, gj0);
                if (acc[mi][3] < 6.f && gi1 != gj0 + 1) local += exact_pair(x, gi1, gj0 + 1);
            }
        }
    }

    if (!diag) local *= 2.f;   // symmetry: (I,J) and (J,I) identical

    // deterministic block reduction
    red[tid] = local;
    __syncthreads();
#pragma unroll
    for (int s = 128; s > 0; s >>= 1) {
        if (tid < s) red[tid] += red[tid + s];
        __syncthreads();
    }
    if (tid == 0) g_partial[bid] = red[0];

    // last CTA performs the deterministic final reduction
    if (tid == 0) {
        __threadfence();
        int prev = atomicAdd(&g_counter, 1);
        amlast = (prev == NTILES - 1);
    }
    __syncthreads();
    if (amlast) {
        float s = 0.f;
        for (int i = tid; i < NTILES; i += 256) s += g_partial[i];
        for (int i = tid; i < NPREP; i += 256) s += g_diagpart[i];
        red[tid] = s;
        __syncthreads();
#pragma unroll
        for (int k = 128; k > 0; k >>= 1) {
            if (tid < k) red[tid] += red[tid + k];
            __syncthreads();
        }
        if (tid == 0) {
            out[0] = 0.25f * red[0];
            g_counter = 0;           // reset for next graph replay
        }
    }
}

// ---------------------------------------------------------------------------
extern "C" void kernel_launch(void* const* d_in, const int* in_sizes, int n_in,
                              void* d_out, int out_size) {
    const float* x = (const float*)d_in[0];   // [1, 32, 8192] fp32, channel-major
    float* out = (float*)d_out;

    prep_kernel<<<NPREP, 64>>>(x);
    tile_kernel<<<NTILES, 256>>>(x, out);
}